// round 12
// baseline (speedup 1.0000x reference)
#include <cuda_runtime.h>
#include <cstdint>

typedef unsigned long long ull;

#define EMB 128
#define INT_EMB 64
#define NRAD 6
#define NSR 42
#define BASIS 8
#define E_EDGES 262144
#define T_TRIP 2097152

// ---------------- scratch (device globals) ------------------------------------
__device__ float g_Wr[NRAD*EMB];
__device__ float g_xji[(size_t)E_EDGES*EMB];
__device__ float g_tmp[(size_t)E_EDGES*EMB];
__device__ float g_upd[(size_t)E_EDGES*EMB];
__device__ float g_xkj2[(size_t)E_EDGES*INT_EMB];
__device__ float g_agg[(size_t)E_EDGES*INT_EMB];
__device__ uint32_t g_Bf[163840];   // all weights, tf32 fragment layout (paired)

// B-frag offsets (u32 elements)
#define OFF_JI   0
#define OFF_KJ   16384
#define OFF_DOWN 32768
#define OFF_UP   40960
#define OFF_B1   49152
#define OFF_B2   65536
#define OFF_FIN  81920
#define OFF_A10  98304
#define OFF_A20  114688
#define OFF_A11  131072
#define OFF_A21  147456

// ---------------- helpers ------------------------------------------------------
__device__ __forceinline__ float silu_f(float x){ return x * (1.0f/(1.0f + __expf(-x))); }
__device__ __forceinline__ uint32_t to_tf32(float f){
    uint32_t u; asm("cvt.rna.tf32.f32 %0, %1;" : "=r"(u) : "f"(f)); return u;
}
__device__ __forceinline__ void mma_tf32(float* c, const uint32_t* a, const uint32_t* b){
    asm volatile("mma.sync.aligned.m16n8k8.row.col.f32.tf32.tf32.f32 "
        "{%0,%1,%2,%3}, {%4,%5,%6,%7}, {%8,%9}, {%0,%1,%2,%3};"
        : "+f"(c[0]), "+f"(c[1]), "+f"(c[2]), "+f"(c[3])
        : "r"(a[0]), "r"(a[1]), "r"(a[2]), "r"(a[3]), "r"(b[0]), "r"(b[1]));
}
__device__ __forceinline__ void ldsm4(uint32_t* d, uint32_t a){
    asm volatile("ldmatrix.sync.aligned.m8n8.x4.shared.b16 {%0,%1,%2,%3}, [%4];"
        : "=r"(d[0]), "=r"(d[1]), "=r"(d[2]), "=r"(d[3]) : "r"(a));
}

// ---------------- K0: fuse W_rbf1 @ W_rbf2 -> g_Wr ----------------------------
__global__ void fuse_wr_kernel(const float* __restrict__ W1, const float* __restrict__ W2) {
    int i = blockIdx.x * blockDim.x + threadIdx.x;
    if (i < NRAD * EMB) {
        int r = i / EMB, n = i % EMB;
        float s = 0.f;
#pragma unroll
        for (int b = 0; b < BASIS; b++) s += W1[r*BASIS + b] * W2[b*EMB + n];
        g_Wr[i] = s;
    }
}

// ---------------- zero g_agg --------------------------------------------------
__global__ void zero_agg_kernel() {
    size_t i = (size_t)blockIdx.x * blockDim.x + threadIdx.x;
    float4 z = {0.f, 0.f, 0.f, 0.f};
    ((float4*)g_agg)[i] = z;
}

// ---------------- B fragment precompute (PAIRED layout) ------------------------
// pair p = nt/2: out[((s*(NT/2) + p)*32 + lane)*4 + (nt&1)*2 + rg]
__global__ void stage_Bg(const float* __restrict__ W, uint32_t* __restrict__ out,
                         int K, int N) {
    int i = blockIdx.x * 128 + threadIdx.x;
    int total = K * (N/4);
    if (i >= total) return;
    int k = i / (N/4), n = (i % (N/4)) * 4;
    const float4 b4 = *(const float4*)&W[(size_t)k*N + n];
    float v[4] = {b4.x, b4.y, b4.z, b4.w};
    int NTP = N/16;
    int s = k >> 3, kk = k & 7, rg = kk >> 2;
#pragma unroll
    for (int e = 0; e < 4; e++) {
        int nn = (n+e) & 7, nt = (n+e) >> 3;
        int ln = (nn << 2) | (kk & 3);
        out[((s*NTP + (nt >> 1))*32 + ln)*4 + (nt & 1)*2 + rg] = to_tf32(v[e]);
    }
}

// ---------------- A staging: row-major, XOR-swizzled, tf32 --------------------
template<int K>
__device__ __forceinline__ void stage_A(const float* __restrict__ A, size_t m0,
                                        uint32_t* __restrict__ As, int tid) {
    constexpr int QPR = K/4;
    for (int i = tid; i < 128*QPR; i += 256) {
        int row = i / QPR, q = i % QPR;
        const float4 a4 = *(const float4*)&A[(m0+row)*K + q*4];
        uint4 t;
        t.x = to_tf32(a4.x); t.y = to_tf32(a4.y); t.z = to_tf32(a4.z); t.w = to_tf32(a4.w);
        int c = (q*4) ^ ((row & 7) << 2);
        *(uint4*)&As[row*K + c] = t;
    }
}

// ---------------- mainloop: ldmatrix A + paired-LDG.128 B ----------------------
// acc: flat [2*WNT][4], acc[i*WNT+j]
template<int K, int NT, int WNT>
__device__ __forceinline__ void mainloop(uint32_t asb, const uint32_t* __restrict__ Bf,
                                         int mp, int nt0, int lane, float (*acc)[4]) {
    const int mi = lane >> 3, r8 = lane & 7;
    const int xoff = (mi >> 1) * 4;
    const int rsel = (mi & 1) * 8;
    const uint32_t swz = (uint32_t)(r8 << 2);
    const uint32_t row0 = (uint32_t)((mp*32 + rsel + r8) * K);
    const uint32_t row1 = row0 + 16u * K;
    constexpr int NTP = NT/2, WNTP = WNT/2;
    const int p0 = nt0 >> 1;
#pragma unroll
    for (int s = 0; s < K/8; s++) {
        const uint32_t col = (uint32_t)(s*8 + xoff) ^ swz;
        uint32_t a0[4], a1[4];
        ldsm4(a0, asb + (row0 + col)*4u);
        ldsm4(a1, asb + (row1 + col)*4u);
#pragma unroll
        for (int jp = 0; jp < WNTP; jp++) {
            const uint4 bb = *(const uint4*)&Bf[((s*NTP + p0 + jp)*32 + lane)*4];
            mma_tf32(acc[2*jp],           a0, (const uint32_t*)&bb.x);
            mma_tf32(acc[WNT + 2*jp],     a1, (const uint32_t*)&bb.x);
            mma_tf32(acc[2*jp + 1],       a0, (const uint32_t*)&bb.z);
            mma_tf32(acc[WNT + 2*jp + 1], a1, (const uint32_t*)&bb.z);
        }
    }
}
template<int W4>
__device__ __forceinline__ void zero_acc(float (*acc)[4]) {
#pragma unroll
    for (int i = 0; i < W4; i++)
#pragma unroll
        for (int e = 0; e < 4; e++) acc[i][e] = 0.f;
}

// ---------------- generic fused GEMM -------------------------------------------
template<int N, int K, bool MUL_RBF, bool ADD_RES>
__global__ __launch_bounds__(256, 2)
void gemm_mma3(const float* __restrict__ A, const uint32_t* __restrict__ Bf,
               const float* __restrict__ bias, const float* __restrict__ res,
               const float* __restrict__ rbf, float* __restrict__ out) {
    constexpr int NT = N/8, WNT = NT/2;
    extern __shared__ __align__(16) uint32_t As[];
    __shared__ float s_Wr[MUL_RBF ? NRAD*EMB : 1];

    const int tid = threadIdx.x, lane = tid & 31, w = tid >> 5;
    const size_t m0 = (size_t)blockIdx.x * 128;
    const int mp = w >> 1;
    const int nt0 = (w & 1) * WNT;

    if (MUL_RBF) for (int i = tid; i < NRAD*EMB; i += 256) s_Wr[i] = g_Wr[i];
    stage_A<K>(A, m0, As, tid);
    __syncthreads();

    const uint32_t asb = (uint32_t)__cvta_generic_to_shared(As);
    const int q = lane >> 2;

    float acc[2*WNT][4];
    zero_acc<2*WNT>(acc);
    mainloop<K, NT, WNT>(asb, Bf, mp, nt0, lane, acc);

#pragma unroll
    for (int i = 0; i < 2; i++) {
        const size_t r_lo = m0 + mp*32 + i*16 + q;
        const size_t r_hi = r_lo + 8;
        float r6lo[NRAD], r6hi[NRAD];
        if (MUL_RBF) {
#pragma unroll
            for (int l = 0; l < NRAD; l++) { r6lo[l] = rbf[r_lo*NRAD + l]; r6hi[l] = rbf[r_hi*NRAD + l]; }
        }
#pragma unroll
        for (int j = 0; j < WNT; j++) {
            const int col = (nt0 + j)*8 + (lane & 3)*2;
            float2 bj = make_float2(0.f, 0.f);
            if (bias) bj = *(const float2*)&bias[col];
            float v00 = silu_f(acc[i*WNT+j][0] + bj.x);
            float v01 = silu_f(acc[i*WNT+j][1] + bj.y);
            float v10 = silu_f(acc[i*WNT+j][2] + bj.x);
            float v11 = silu_f(acc[i*WNT+j][3] + bj.y);
            if (MUL_RBF) {
                float e00=0.f,e01=0.f,e10=0.f,e11=0.f;
#pragma unroll
                for (int l = 0; l < NRAD; l++) {
                    const float w0 = s_Wr[l*EMB + col], w1 = s_Wr[l*EMB + col + 1];
                    e00 += r6lo[l]*w0; e01 += r6lo[l]*w1;
                    e10 += r6hi[l]*w0; e11 += r6hi[l]*w1;
                }
                v00 *= e00; v01 *= e01; v10 *= e10; v11 *= e11;
            }
            if (ADD_RES) {
                const float2 rl = *(const float2*)&res[r_lo*N + col];
                const float2 rh = *(const float2*)&res[r_hi*N + col];
                v00 += rl.x; v01 += rl.y; v10 += rh.x; v11 += rh.y;
            }
            float2 o0; o0.x = v00; o0.y = v01;
            float2 o1; o1.x = v10; o1.y = v11;
            *(float2*)&out[r_lo*N + col] = o0;
            *(float2*)&out[r_hi*N + col] = o1;
        }
    }
}

// ---------------- fused ji+kj kernel -------------------------------------------
__global__ __launch_bounds__(256, 2)
void gemm2_mma3(const float* __restrict__ m,
                const uint32_t* __restrict__ Bf_ji, const uint32_t* __restrict__ Bf_kj,
                const float* __restrict__ b_ji, const float* __restrict__ b_kj,
                const float* __restrict__ rbf,
                float* __restrict__ out_ji, float* __restrict__ out_kj) {
    constexpr int NT = 16, WNT = 8;
    extern __shared__ __align__(16) uint32_t As[];
    __shared__ float s_Wr[NRAD*EMB];

    const int tid = threadIdx.x, lane = tid & 31, w = tid >> 5;
    const size_t m0 = (size_t)blockIdx.x * 128;
    const int mp = w >> 1;
    const int nt0 = (w & 1) * WNT;

    for (int i = tid; i < NRAD*EMB; i += 256) s_Wr[i] = g_Wr[i];
    stage_A<128>(m, m0, As, tid);
    __syncthreads();

    const uint32_t asb = (uint32_t)__cvta_generic_to_shared(As);
    const int q = lane >> 2;

    float acc[16][4];

    // ======== phase 1: x_ji ========
    zero_acc<16>(acc);
    mainloop<128, NT, WNT>(asb, Bf_ji, mp, nt0, lane, acc);
#pragma unroll
    for (int i = 0; i < 2; i++) {
        const size_t r_lo = m0 + mp*32 + i*16 + q;
        const size_t r_hi = r_lo + 8;
#pragma unroll
        for (int j = 0; j < WNT; j++) {
            const int col = (nt0 + j)*8 + (lane & 3)*2;
            const float2 bj = *(const float2*)&b_ji[col];
            float2 o0, o1;
            o0.x = silu_f(acc[i*WNT+j][0] + bj.x);
            o0.y = silu_f(acc[i*WNT+j][1] + bj.y);
            o1.x = silu_f(acc[i*WNT+j][2] + bj.x);
            o1.y = silu_f(acc[i*WNT+j][3] + bj.y);
            *(float2*)&out_ji[r_lo*128 + col] = o0;
            *(float2*)&out_ji[r_hi*128 + col] = o1;
        }
    }

    // ======== phase 2: tmp (kj * rbf_env) ========
    zero_acc<16>(acc);
    mainloop<128, NT, WNT>(asb, Bf_kj, mp, nt0, lane, acc);
#pragma unroll
    for (int i = 0; i < 2; i++) {
        const size_t r_lo = m0 + mp*32 + i*16 + q;
        const size_t r_hi = r_lo + 8;
        float r6lo[NRAD], r6hi[NRAD];
#pragma unroll
        for (int l = 0; l < NRAD; l++) { r6lo[l] = rbf[r_lo*NRAD + l]; r6hi[l] = rbf[r_hi*NRAD + l]; }
#pragma unroll
        for (int j = 0; j < WNT; j++) {
            const int col = (nt0 + j)*8 + (lane & 3)*2;
            const float2 bj = *(const float2*)&b_kj[col];
            float e00=0.f,e01=0.f,e10=0.f,e11=0.f;
#pragma unroll
            for (int l = 0; l < NRAD; l++) {
                const float w0 = s_Wr[l*EMB + col], w1 = s_Wr[l*EMB + col + 1];
                e00 += r6lo[l]*w0; e01 += r6lo[l]*w1;
                e10 += r6hi[l]*w0; e11 += r6hi[l]*w1;
            }
            float2 o0, o1;
            o0.x = silu_f(acc[i*WNT+j][0] + bj.x) * e00;
            o0.y = silu_f(acc[i*WNT+j][1] + bj.y) * e01;
            o1.x = silu_f(acc[i*WNT+j][2] + bj.x) * e10;
            o1.y = silu_f(acc[i*WNT+j][3] + bj.y) * e11;
            *(float2*)&out_kj[r_lo*128 + col] = o0;
            *(float2*)&out_kj[r_hi*128 + col] = o1;
        }
    }
}

// ---------------- fused residual block -----------------------------------------
__global__ __launch_bounds__(256, 2)
void resid_mma3(const float* __restrict__ X,
                const uint32_t* __restrict__ B1f, const float* __restrict__ b1,
                const uint32_t* __restrict__ B2f, const float* __restrict__ b2,
                float* __restrict__ out) {
    constexpr int NT = 16, WNT = 8;
    extern __shared__ __align__(16) uint32_t As[];

    const int tid = threadIdx.x, lane = tid & 31, w = tid >> 5;
    const size_t m0 = (size_t)blockIdx.x * 128;
    const int mp = w >> 1;
    const int nt0 = (w & 1) * WNT;

    stage_A<128>(X, m0, As, tid);
    __syncthreads();

    const uint32_t asb = (uint32_t)__cvta_generic_to_shared(As);
    const int q = lane >> 2;
    const int sw = q << 2;

    float acc[16][4];
    zero_acc<16>(acc);
    mainloop<128, NT, WNT>(asb, B1f, mp, nt0, lane, acc);
    __syncthreads();

    // epilogue1: h = silu(acc + b1) -> back into As
#pragma unroll
    for (int i = 0; i < 2; i++) {
        const int rl = mp*32 + i*16 + q;
#pragma unroll
        for (int j = 0; j < WNT; j++) {
            const int cj = (nt0 + j)*8 + (lane & 3)*2;
            const float2 bj = *(const float2*)&b1[cj];
            float v[4];
            v[0] = silu_f(acc[i*WNT+j][0] + bj.x);
            v[1] = silu_f(acc[i*WNT+j][1] + bj.y);
            v[2] = silu_f(acc[i*WNT+j][2] + bj.x);
            v[3] = silu_f(acc[i*WNT+j][3] + bj.y);
#pragma unroll
            for (int e = 0; e < 4; e++) {
                const int r = rl + ((e >> 1) ? 8 : 0);
                const int c = cj + (e & 1);
                As[r*128 + (c ^ sw)] = to_tf32(v[e]);
            }
        }
    }
    __syncthreads();

    zero_acc<16>(acc);
    mainloop<128, NT, WNT>(asb, B2f, mp, nt0, lane, acc);

    // epilogue2: out = X + silu(acc + b2)
#pragma unroll
    for (int i = 0; i < 2; i++) {
        const size_t r_lo = m0 + mp*32 + i*16 + q;
        const size_t r_hi = r_lo + 8;
#pragma unroll
        for (int j = 0; j < WNT; j++) {
            const int col = (nt0 + j)*8 + (lane & 3)*2;
            const float2 bj = *(const float2*)&b2[col];
            const float2 xl = *(const float2*)&X[r_lo*128 + col];
            const float2 xh = *(const float2*)&X[r_hi*128 + col];
            float2 o0, o1;
            o0.x = xl.x + silu_f(acc[i*WNT+j][0] + bj.x);
            o0.y = xl.y + silu_f(acc[i*WNT+j][1] + bj.y);
            o1.x = xh.x + silu_f(acc[i*WNT+j][2] + bj.x);
            o1.y = xh.y + silu_f(acc[i*WNT+j][3] + bj.y);
            *(float2*)&out[r_lo*128 + col] = o0;
            *(float2*)&out[r_hi*128 + col] = o1;
        }
    }
}

// ---------------- triplet kernel (unchanged, passes) ---------------------------
__global__ __launch_bounds__(256)
void triplet_kernel(const float* __restrict__ sbf,
                    const int* __restrict__ src_idx,
                    const int* __restrict__ dst_idx,
                    const float* __restrict__ W1,
                    const float* __restrict__ W2) {
    __shared__ float sbf_s[16*NSR];
    __shared__ float W1s[NSR*BASIS];
    __shared__ __align__(16) float W2s[BASIS*INT_EMB];
    __shared__ float t8[16][BASIS];

    const int tid = threadIdx.x;
    for (int i = tid; i < NSR*BASIS; i += 256) W1s[i] = W1[i];
    for (int i = tid; i < BASIS*INT_EMB; i += 256) W2s[i] = W2[i];

    const int ngroups = T_TRIP / 16;
    const int half = tid >> 4;
    const int l16  = tid & 15;

    for (int g = blockIdx.x; g < ngroups; g += gridDim.x) {
        const size_t base = (size_t)g * (16*NSR);
        for (int i = tid; i < 16*NSR; i += 256) sbf_s[i] = sbf[base + i];
        __syncthreads();

        if (tid < 128) {
            int tt = tid >> 3, j = tid & 7;
            float s = 0.f;
#pragma unroll
            for (int r = 0; r < NSR; r++) s += sbf_s[tt*NSR + r] * W1s[r*BASIS + j];
            t8[tt][j] = s;
        }
        __syncthreads();

        const int t = g*16 + half;
        const int src = src_idx[t];
        const int dst = dst_idx[t];

        float4 a = {0.f, 0.f, 0.f, 0.f};
#pragma unroll
        for (int j = 0; j < BASIS; j++) {
            const float tv = t8[half][j];
            const float4 w = *(const float4*)&W2s[j*INT_EMB + l16*4];
            a.x += tv*w.x; a.y += tv*w.y; a.z += tv*w.z; a.w += tv*w.w;
        }
        const float4 xk = *(const float4*)(g_xkj2 + (size_t)src*INT_EMB + l16*4);
        a.x *= xk.x; a.y *= xk.y; a.z *= xk.z; a.w *= xk.w;

        atomicAdd((float4*)(g_agg + (size_t)dst*INT_EMB + l16*4), a);
        __syncthreads();
    }
}

// ---------------- host launcher ----------------------------------------------
extern "C" void kernel_launch(void* const* d_in, const int* in_sizes, int n_in,
                              void* d_out, int out_size) {
    const float* m       = (const float*)d_in[0];
    const float* rbf     = (const float*)d_in[1];
    const float* sbf     = (const float*)d_in[2];
    const int*   src_idx = (const int*)d_in[3];
    const int*   dst_idx = (const int*)d_in[4];
    const float* W_rbf1  = (const float*)d_in[5];
    const float* W_rbf2  = (const float*)d_in[6];
    const float* W_sbf1  = (const float*)d_in[7];
    const float* W_sbf2  = (const float*)d_in[8];
    const float* W_ji    = (const float*)d_in[9];
    const float* b_ji    = (const float*)d_in[10];
    const float* W_kj    = (const float*)d_in[11];
    const float* b_kj    = (const float*)d_in[12];
    const float* W_down  = (const float*)d_in[13];
    const float* W_up    = (const float*)d_in[14];
    const float* Wb1     = (const float*)d_in[15];
    const float* bb1     = (const float*)d_in[16];
    const float* Wb2     = (const float*)d_in[17];
    const float* bb2     = (const float*)d_in[18];
    const float* W_final = (const float*)d_in[19];
    const float* b_final = (const float*)d_in[20];
    const float* Wa1     = (const float*)d_in[21];
    const float* ba1     = (const float*)d_in[22];
    const float* Wa2     = (const float*)d_in[23];
    const float* ba2     = (const float*)d_in[24];
    float* out = (float*)d_out;

    float *p_xji, *p_tmp, *p_upd, *p_xkj2, *p_agg;
    uint32_t* p_Bf;
    cudaGetSymbolAddress((void**)&p_xji,  g_xji);
    cudaGetSymbolAddress((void**)&p_tmp,  g_tmp);
    cudaGetSymbolAddress((void**)&p_upd,  g_upd);
    cudaGetSymbolAddress((void**)&p_xkj2, g_xkj2);
    cudaGetSymbolAddress((void**)&p_agg,  g_agg);
    cudaGetSymbolAddress((void**)&p_Bf,   g_Bf);

    const int GB = E_EDGES / 128;     // 2048
    const int SM_K128 = 128*128*4;    // 65536
    const int SM_K64  = 128*64*4;     // 32768

    cudaFuncSetAttribute((const void*)gemm2_mma3, cudaFuncAttributeMaxDynamicSharedMemorySize, SM_K128);
    cudaFuncSetAttribute((const void*)gemm_mma3<128,128,false,true >, cudaFuncAttributeMaxDynamicSharedMemorySize, SM_K128);
    cudaFuncSetAttribute((const void*)gemm_mma3<64 ,128,false,false>, cudaFuncAttributeMaxDynamicSharedMemorySize, SM_K128);
    cudaFuncSetAttribute((const void*)gemm_mma3<128,64 ,false,true >, cudaFuncAttributeMaxDynamicSharedMemorySize, SM_K64);
    cudaFuncSetAttribute((const void*)resid_mma3, cudaFuncAttributeMaxDynamicSharedMemorySize, SM_K128);

    // ---- launch order: my #4 = gemm2_mma3 (overall #6 for ncu -s 5 -c 1) ----
    stage_Bg<<<128, 128>>>(W_ji, p_Bf + OFF_JI, 128, 128);            // 1
    stage_Bg<<<128, 128>>>(W_kj, p_Bf + OFF_KJ, 128, 128);            // 2
    fuse_wr_kernel<<<3, 256>>>(W_rbf1, W_rbf2);                       // 3

    // x_ji & tmp in one pass (shared A staging)                      // 4 <- profiled
    gemm2_mma3<<<GB,256,SM_K128>>>(m, p_Bf + OFF_JI, p_Bf + OFF_KJ,
                                   b_ji, b_kj, rbf, p_xji, p_tmp);

    zero_agg_kernel<<<(E_EDGES*INT_EMB/4)/256, 256>>>();              // 5
    stage_Bg<<<64 , 128>>>(W_down, p_Bf + OFF_DOWN, 128, 64);         // 6
    stage_Bg<<<64 , 128>>>(W_up,    p_Bf + OFF_UP,   64 , 128);
    stage_Bg<<<128, 128>>>(Wb1,     p_Bf + OFF_B1,   128, 128);
    stage_Bg<<<128, 128>>>(Wb2,     p_Bf + OFF_B2,   128, 128);
    stage_Bg<<<128, 128>>>(W_final, p_Bf + OFF_FIN,  128, 128);
    stage_Bg<<<128, 128>>>(Wa1,           p_Bf + OFF_A10, 128, 128);
    stage_Bg<<<128, 128>>>(Wa2,           p_Bf + OFF_A20, 128, 128);
    stage_Bg<<<128, 128>>>(Wa1 + 128*128, p_Bf + OFF_A11, 128, 128);
    stage_Bg<<<128, 128>>>(Wa2 + 128*128, p_Bf + OFF_A21, 128, 128);

    // x_kj2 = silu(tmp @ W_down)
    gemm_mma3<64 ,128,false,false><<<GB,256,SM_K128>>>(p_tmp, p_Bf + OFF_DOWN, nullptr, nullptr, nullptr, p_xkj2);

    // triplet message + segment sum
    triplet_kernel<<<4096, 256>>>(sbf, src_idx, dst_idx, W_sbf1, W_sbf2);

    // upd = x_ji + silu(agg @ W_up)
    gemm_mma3<128,64 ,false,true ><<<GB,256,SM_K64>>>(p_agg, p_Bf + OFF_UP, nullptr, p_xji, nullptr, p_upd);
    // residual-before (N_BEFORE=1), in-place
    resid_mma3<<<GB,256,SM_K128>>>(p_upd, p_Bf + OFF_B1, bb1, p_Bf + OFF_B2, bb2, p_upd);
    // final: out = m + silu(upd @ W_final + b_final)
    gemm_mma3<128,128,false,true ><<<GB,256,SM_K128>>>(p_upd, p_Bf + OFF_FIN, b_final, m, nullptr, out);
    // residual-after (N_AFTER=2), in-place on out
    resid_mma3<<<GB,256,SM_K128>>>(out, p_Bf + OFF_A10, ba1,       p_Bf + OFF_A20, ba2,       out);
    resid_mma3<<<GB,256,SM_K128>>>(out, p_Bf + OFF_A11, ba1 + 128, p_Bf + OFF_A21, ba2 + 128, out);
}

// round 14
// speedup vs baseline: 1.2919x; 1.2919x over previous
#include <cuda_runtime.h>
#include <cstdint>

typedef unsigned long long ull;

#define EMB 128
#define INT_EMB 64
#define NRAD 6
#define NSR 42
#define BASIS 8
#define E_EDGES 262144
#define T_TRIP 2097152
#define CHUNK_S 4   // s-steps per B chunk

// ---------------- scratch (device globals) ------------------------------------
__device__ float g_Wr[NRAD*EMB];
__device__ float g_xji[(size_t)E_EDGES*EMB];
__device__ float g_tmp[(size_t)E_EDGES*EMB];
__device__ float g_upd[(size_t)E_EDGES*EMB];
__device__ float g_xkj2[(size_t)E_EDGES*INT_EMB];
__device__ float g_agg[(size_t)E_EDGES*INT_EMB];
__device__ uint32_t g_Bf[163840];   // all weights, tf32 fragment layout

// B-frag offsets (u32 elements)
#define OFF_JI   0
#define OFF_KJ   16384
#define OFF_DOWN 32768
#define OFF_UP   40960
#define OFF_B1   49152
#define OFF_B2   65536
#define OFF_FIN  81920
#define OFF_A10  98304
#define OFF_A20  114688
#define OFF_A11  131072
#define OFF_A21  147456

// ---------------- helpers ------------------------------------------------------
__device__ __forceinline__ float silu_f(float x){ return x * (1.0f/(1.0f + __expf(-x))); }
__device__ __forceinline__ uint32_t to_tf32(float f){
    uint32_t u; asm("cvt.rna.tf32.f32 %0, %1;" : "=r"(u) : "f"(f)); return u;
}
__device__ __forceinline__ void mma_tf32(float* c, const uint32_t* a, const uint32_t* b){
    asm volatile("mma.sync.aligned.m16n8k8.row.col.f32.tf32.tf32.f32 "
        "{%0,%1,%2,%3}, {%4,%5,%6,%7}, {%8,%9}, {%0,%1,%2,%3};"
        : "+f"(c[0]), "+f"(c[1]), "+f"(c[2]), "+f"(c[3])
        : "r"(a[0]), "r"(a[1]), "r"(a[2]), "r"(a[3]), "r"(b[0]), "r"(b[1]));
}

// ---------------- K0: fuse W_rbf1 @ W_rbf2 -> g_Wr ----------------------------
__global__ void fuse_wr_kernel(const float* __restrict__ W1, const float* __restrict__ W2) {
    int i = blockIdx.x * blockDim.x + threadIdx.x;
    if (i < NRAD * EMB) {
        int r = i / EMB, n = i % EMB;
        float s = 0.f;
#pragma unroll
        for (int b = 0; b < BASIS; b++) s += W1[r*BASIS + b] * W2[b*EMB + n];
        g_Wr[i] = s;
    }
}

// ---------------- zero g_agg --------------------------------------------------
__global__ void zero_agg_kernel() {
    size_t i = (size_t)blockIdx.x * blockDim.x + threadIdx.x;
    float4 z = {0.f, 0.f, 0.f, 0.f};
    ((float4*)g_agg)[i] = z;
}

// ---------------- B fragment precompute (R10 unpaired layout) -------------------
__global__ void stage_Bg(const float* __restrict__ W, uint32_t* __restrict__ out,
                         int K, int N) {
    int i = blockIdx.x * 128 + threadIdx.x;
    int total = K * (N/4);
    if (i >= total) return;
    int k = i / (N/4), n = (i % (N/4)) * 4;
    const float4 b4 = *(const float4*)&W[(size_t)k*N + n];
    float v[4] = {b4.x, b4.y, b4.z, b4.w};
    int NT = N/8;
    int s = k >> 3, kk = k & 7, rg = kk >> 2;
#pragma unroll
    for (int e = 0; e < 4; e++) {
        int nn = (n+e) & 7, nt = (n+e) >> 3;
        int ln = (nn << 2) | (kk & 3);
        out[((s*NT + nt)*32 + ln)*2 + rg] = to_tf32(v[e]);
    }
}

// ---------------- A staging: row-major, XOR-swizzled, tf32 --------------------
template<int K>
__device__ __forceinline__ void stage_A(const float* __restrict__ A, size_t m0,
                                        uint32_t* __restrict__ As, int tid) {
    constexpr int QPR = K/4;
    for (int i = tid; i < 128*QPR; i += 256) {
        int row = i / QPR, q = i % QPR;
        const float4 a4 = *(const float4*)&A[(m0+row)*K + q*4];
        uint4 t;
        t.x = to_tf32(a4.x); t.y = to_tf32(a4.y); t.z = to_tf32(a4.z); t.w = to_tf32(a4.w);
        int c = (q*4) ^ ((row & 7) << 2);
        *(uint4*)&As[row*K + c] = t;
    }
}

// ---------------- cp.async chunk copy (gmem frags -> smem buffer) ---------------
template<int CHUNK_U32>
__device__ __forceinline__ void cp_chunk(uint32_t* __restrict__ Bs,
                                         const uint32_t* __restrict__ Bf, int tid) {
    constexpr int NCP = (CHUNK_U32*4) / (256*16);   // 16B copies per thread
    const uint32_t sdst = (uint32_t)__cvta_generic_to_shared(Bs);
#pragma unroll
    for (int i = 0; i < NCP; i++) {
        const int off = (tid + i*256) * 16;
        asm volatile("cp.async.cg.shared.global [%0], [%1], 16;"
            :: "r"(sdst + (uint32_t)off), "l"((const char*)Bf + off) : "memory");
    }
}

// ---------------- mainloop: A from SMEM (R10 scalar LDS), B via cp.async chunks -
// acc0 = rows mp*32+[0,16), acc1 = rows mp*32+[16,32)
template<int K, int NT, int WNT>
__device__ __forceinline__ void mainloop_ca(const uint32_t* __restrict__ As,
                                            uint32_t* __restrict__ Bs,
                                            const uint32_t* __restrict__ Bf,
                                            int mp, int nt0, int lane, int tid,
                                            float (*acc0)[4], float (*acc1)[4]) {
    constexpr int KS = K/8;
    constexpr int C  = KS/CHUNK_S;
    constexpr int CHUNK_U32 = CHUNK_S*NT*64;
    const int q = lane >> 2, sw = q << 2;
    const int rowA0 = (mp*32 + q) * K;
    const int rowA1 = (mp*32 + 16 + q) * K;

    cp_chunk<CHUNK_U32>(Bs, Bf, tid);
    asm volatile("cp.async.commit_group;" ::: "memory");

#pragma unroll
    for (int c = 0; c < C; c++) {
        if (c + 1 < C) {
            cp_chunk<CHUNK_U32>(Bs + ((c+1)&1)*CHUNK_U32, Bf + (c+1)*CHUNK_U32, tid);
            asm volatile("cp.async.commit_group;" ::: "memory");
            asm volatile("cp.async.wait_group 1;" ::: "memory");
        } else {
            asm volatile("cp.async.wait_group 0;" ::: "memory");
        }
        __syncthreads();
        const uint32_t* Bc = Bs + (c&1)*CHUNK_U32;
#pragma unroll
        for (int sl = 0; sl < CHUNK_S; sl++) {
            const int s = c*CHUNK_S + sl;
            const int c0 = s*8 + (lane & 3);
            uint32_t a[2][4];
            a[0][0] = As[rowA0       + (c0 ^ sw)];
            a[0][1] = As[rowA0 + 8*K + (c0 ^ sw)];
            a[0][2] = As[rowA0       + ((c0+4) ^ sw)];
            a[0][3] = As[rowA0 + 8*K + ((c0+4) ^ sw)];
            a[1][0] = As[rowA1       + (c0 ^ sw)];
            a[1][1] = As[rowA1 + 8*K + (c0 ^ sw)];
            a[1][2] = As[rowA1       + ((c0+4) ^ sw)];
            a[1][3] = As[rowA1 + 8*K + ((c0+4) ^ sw)];
#pragma unroll
            for (int j = 0; j < WNT; j++) {
                uint2 b = *(const uint2*)&Bc[((sl*NT + nt0 + j)*32 + lane)*2];
                mma_tf32(acc0[j], a[0], (const uint32_t*)&b);
                mma_tf32(acc1[j], a[1], (const uint32_t*)&b);
            }
        }
        __syncthreads();
    }
}
template<int W4>
__device__ __forceinline__ void zero_acc(float (*acc)[4]) {
#pragma unroll
    for (int i = 0; i < W4; i++)
#pragma unroll
        for (int e = 0; e < 4; e++) acc[i][e] = 0.f;
}

// ---------------- generic fused GEMM -------------------------------------------
template<int N, int K, bool MUL_RBF, bool ADD_RES>
__global__ __launch_bounds__(256, 2)
void gemm_mma3(const float* __restrict__ A, const uint32_t* __restrict__ Bf,
               const float* __restrict__ bias, const float* __restrict__ res,
               const float* __restrict__ rbf, float* __restrict__ out) {
    constexpr int NT = N/8, WNT = NT/2;
    extern __shared__ __align__(16) uint32_t dyn[];
    uint32_t* As = dyn;
    uint32_t* Bs = dyn + 128*K;
    __shared__ float s_Wr[MUL_RBF ? NRAD*EMB : 1];

    const int tid = threadIdx.x, lane = tid & 31, w = tid >> 5;
    const size_t m0 = (size_t)blockIdx.x * 128;
    const int mp = w >> 1;
    const int nt0 = (w & 1) * WNT;
    const int q = lane >> 2;

    if (MUL_RBF) for (int i = tid; i < NRAD*EMB; i += 256) s_Wr[i] = g_Wr[i];
    stage_A<K>(A, m0, As, tid);
    __syncthreads();

    float acc[2][WNT][4];
    zero_acc<2*WNT>(&acc[0][0]);
    mainloop_ca<K, NT, WNT>(As, Bs, Bf, mp, nt0, lane, tid, acc[0], acc[1]);

#pragma unroll
    for (int i = 0; i < 2; i++) {
        const size_t r_lo = m0 + mp*32 + i*16 + q;
        const size_t r_hi = r_lo + 8;
        float r6lo[NRAD], r6hi[NRAD];
        if (MUL_RBF) {
#pragma unroll
            for (int l = 0; l < NRAD; l++) { r6lo[l] = rbf[r_lo*NRAD + l]; r6hi[l] = rbf[r_hi*NRAD + l]; }
        }
#pragma unroll
        for (int j = 0; j < WNT; j++) {
            const int col = (nt0 + j)*8 + (lane & 3)*2;
            float2 bj = make_float2(0.f, 0.f);
            if (bias) bj = *(const float2*)&bias[col];
            float v00 = silu_f(acc[i][j][0] + bj.x);
            float v01 = silu_f(acc[i][j][1] + bj.y);
            float v10 = silu_f(acc[i][j][2] + bj.x);
            float v11 = silu_f(acc[i][j][3] + bj.y);
            if (MUL_RBF) {
                float e00=0.f,e01=0.f,e10=0.f,e11=0.f;
#pragma unroll
                for (int l = 0; l < NRAD; l++) {
                    const float w0 = s_Wr[l*EMB + col], w1 = s_Wr[l*EMB + col + 1];
                    e00 += r6lo[l]*w0; e01 += r6lo[l]*w1;
                    e10 += r6hi[l]*w0; e11 += r6hi[l]*w1;
                }
                v00 *= e00; v01 *= e01; v10 *= e10; v11 *= e11;
            }
            if (ADD_RES) {
                const float2 rl = *(const float2*)&res[r_lo*N + col];
                const float2 rh = *(const float2*)&res[r_hi*N + col];
                v00 += rl.x; v01 += rl.y; v10 += rh.x; v11 += rh.y;
            }
            float2 o0; o0.x = v00; o0.y = v01;
            float2 o1; o1.x = v10; o1.y = v11;
            *(float2*)&out[r_lo*N + col] = o0;
            *(float2*)&out[r_hi*N + col] = o1;
        }
    }
}

// ---------------- fused ji+kj kernel -------------------------------------------
__global__ __launch_bounds__(256, 2)
void gemm2_mma3(const float* __restrict__ m,
                const uint32_t* __restrict__ Bf_ji, const uint32_t* __restrict__ Bf_kj,
                const float* __restrict__ b_ji, const float* __restrict__ b_kj,
                const float* __restrict__ rbf,
                float* __restrict__ out_ji, float* __restrict__ out_kj) {
    constexpr int NT = 16, WNT = 8;
    extern __shared__ __align__(16) uint32_t dyn[];
    uint32_t* As = dyn;
    uint32_t* Bs = dyn + 128*128;
    __shared__ float s_Wr[NRAD*EMB];

    const int tid = threadIdx.x, lane = tid & 31, w = tid >> 5;
    const size_t m0 = (size_t)blockIdx.x * 128;
    const int mp = w >> 1;
    const int nt0 = (w & 1) * WNT;
    const int q = lane >> 2;

    for (int i = tid; i < NRAD*EMB; i += 256) s_Wr[i] = g_Wr[i];
    stage_A<128>(m, m0, As, tid);
    __syncthreads();

    float acc[2][WNT][4];

    // ======== phase 1: x_ji ========
    zero_acc<2*WNT>(&acc[0][0]);
    mainloop_ca<128, NT, WNT>(As, Bs, Bf_ji, mp, nt0, lane, tid, acc[0], acc[1]);
#pragma unroll
    for (int i = 0; i < 2; i++) {
        const size_t r_lo = m0 + mp*32 + i*16 + q;
        const size_t r_hi = r_lo + 8;
#pragma unroll
        for (int j = 0; j < WNT; j++) {
            const int col = (nt0 + j)*8 + (lane & 3)*2;
            const float2 bj = *(const float2*)&b_ji[col];
            float2 o0, o1;
            o0.x = silu_f(acc[i][j][0] + bj.x);
            o0.y = silu_f(acc[i][j][1] + bj.y);
            o1.x = silu_f(acc[i][j][2] + bj.x);
            o1.y = silu_f(acc[i][j][3] + bj.y);
            *(float2*)&out_ji[r_lo*128 + col] = o0;
            *(float2*)&out_ji[r_hi*128 + col] = o1;
        }
    }

    // ======== phase 2: tmp (kj * rbf_env) ========
    zero_acc<2*WNT>(&acc[0][0]);
    mainloop_ca<128, NT, WNT>(As, Bs, Bf_kj, mp, nt0, lane, tid, acc[0], acc[1]);
#pragma unroll
    for (int i = 0; i < 2; i++) {
        const size_t r_lo = m0 + mp*32 + i*16 + q;
        const size_t r_hi = r_lo + 8;
        float r6lo[NRAD], r6hi[NRAD];
#pragma unroll
        for (int l = 0; l < NRAD; l++) { r6lo[l] = rbf[r_lo*NRAD + l]; r6hi[l] = rbf[r_hi*NRAD + l]; }
#pragma unroll
        for (int j = 0; j < WNT; j++) {
            const int col = (nt0 + j)*8 + (lane & 3)*2;
            const float2 bj = *(const float2*)&b_kj[col];
            float e00=0.f,e01=0.f,e10=0.f,e11=0.f;
#pragma unroll
            for (int l = 0; l < NRAD; l++) {
                const float w0 = s_Wr[l*EMB + col], w1 = s_Wr[l*EMB + col + 1];
                e00 += r6lo[l]*w0; e01 += r6lo[l]*w1;
                e10 += r6hi[l]*w0; e11 += r6hi[l]*w1;
            }
            float2 o0, o1;
            o0.x = silu_f(acc[i][j][0] + bj.x) * e00;
            o0.y = silu_f(acc[i][j][1] + bj.y) * e01;
            o1.x = silu_f(acc[i][j][2] + bj.x) * e10;
            o1.y = silu_f(acc[i][j][3] + bj.y) * e11;
            *(float2*)&out_kj[r_lo*128 + col] = o0;
            *(float2*)&out_kj[r_hi*128 + col] = o1;
        }
    }
}

// ---------------- fused residual block -----------------------------------------
__global__ __launch_bounds__(256, 2)
void resid_mma3(const float* __restrict__ X,
                const uint32_t* __restrict__ B1f, const float* __restrict__ b1,
                const uint32_t* __restrict__ B2f, const float* __restrict__ b2,
                float* __restrict__ out) {
    constexpr int NT = 16, WNT = 8;
    extern __shared__ __align__(16) uint32_t dyn[];
    uint32_t* As = dyn;
    uint32_t* Bs = dyn + 128*128;

    const int tid = threadIdx.x, lane = tid & 31, w = tid >> 5;
    const size_t m0 = (size_t)blockIdx.x * 128;
    const int mp = w >> 1;
    const int nt0 = (w & 1) * WNT;
    const int q = lane >> 2;
    const int sw = q << 2;

    stage_A<128>(X, m0, As, tid);
    __syncthreads();

    float acc[2][WNT][4];
    zero_acc<2*WNT>(&acc[0][0]);
    mainloop_ca<128, NT, WNT>(As, Bs, B1f, mp, nt0, lane, tid, acc[0], acc[1]);
    // mainloop ends with __syncthreads(): all A reads done

    // epilogue1: h = silu(acc + b1) -> back into As
#pragma unroll
    for (int i = 0; i < 2; i++) {
        const int rl = mp*32 + i*16 + q;
#pragma unroll
        for (int j = 0; j < WNT; j++) {
            const int cj = (nt0 + j)*8 + (lane & 3)*2;
            const float2 bj = *(const float2*)&b1[cj];
            float v[4];
            v[0] = silu_f(acc[i][j][0] + bj.x);
            v[1] = silu_f(acc[i][j][1] + bj.y);
            v[2] = silu_f(acc[i][j][2] + bj.x);
            v[3] = silu_f(acc[i][j][3] + bj.y);
#pragma unroll
            for (int e = 0; e < 4; e++) {
                const int r = rl + ((e >> 1) ? 8 : 0);
                const int c = cj + (e & 1);
                As[r*128 + (c ^ sw)] = to_tf32(v[e]);
            }
        }
    }
    __syncthreads();

    zero_acc<2*WNT>(&acc[0][0]);
    mainloop_ca<128, NT, WNT>(As, Bs, B2f, mp, nt0, lane, tid, acc[0], acc[1]);

    // epilogue2: out = X + silu(acc + b2)
#pragma unroll
    for (int i = 0; i < 2; i++) {
        const size_t r_lo = m0 + mp*32 + i*16 + q;
        const size_t r_hi = r_lo + 8;
#pragma unroll
        for (int j = 0; j < WNT; j++) {
            const int col = (nt0 + j)*8 + (lane & 3)*2;
            const float2 bj = *(const float2*)&b2[col];
            const float2 xl = *(const float2*)&X[r_lo*128 + col];
            const float2 xh = *(const float2*)&X[r_hi*128 + col];
            float2 o0, o1;
            o0.x = xl.x + silu_f(acc[i][j][0] + bj.x);
            o0.y = xl.y + silu_f(acc[i][j][1] + bj.y);
            o1.x = xh.x + silu_f(acc[i][j][2] + bj.x);
            o1.y = xh.y + silu_f(acc[i][j][3] + bj.y);
            *(float2*)&out[r_lo*128 + col] = o0;
            *(float2*)&out[r_hi*128 + col] = o1;
        }
    }
}

// ---------------- triplet kernel (unchanged, passes) ---------------------------
__global__ __launch_bounds__(256)
void triplet_kernel(const float* __restrict__ sbf,
                    const int* __restrict__ src_idx,
                    const int* __restrict__ dst_idx,
                    const float* __restrict__ W1,
                    const float* __restrict__ W2) {
    __shared__ float sbf_s[16*NSR];
    __shared__ float W1s[NSR*BASIS];
    __shared__ __align__(16) float W2s[BASIS*INT_EMB];
    __shared__ float t8[16][BASIS];

    const int tid = threadIdx.x;
    for (int i = tid; i < NSR*BASIS; i += 256) W1s[i] = W1[i];
    for (int i = tid; i < BASIS*INT_EMB; i += 256) W2s[i] = W2[i];

    const int ngroups = T_TRIP / 16;
    const int half = tid >> 4;
    const int l16  = tid & 15;

    for (int g = blockIdx.x; g < ngroups; g += gridDim.x) {
        const size_t base = (size_t)g * (16*NSR);
        for (int i = tid; i < 16*NSR; i += 256) sbf_s[i] = sbf[base + i];
        __syncthreads();

        if (tid < 128) {
            int tt = tid >> 3, j = tid & 7;
            float s = 0.f;
#pragma unroll
            for (int r = 0; r < NSR; r++) s += sbf_s[tt*NSR + r] * W1s[r*BASIS + j];
            t8[tt][j] = s;
        }
        __syncthreads();

        const int t = g*16 + half;
        const int src = src_idx[t];
        const int dst = dst_idx[t];

        float4 a = {0.f, 0.f, 0.f, 0.f};
#pragma unroll
        for (int j = 0; j < BASIS; j++) {
            const float tv = t8[half][j];
            const float4 w = *(const float4*)&W2s[j*INT_EMB + l16*4];
            a.x += tv*w.x; a.y += tv*w.y; a.z += tv*w.z; a.w += tv*w.w;
        }
        const float4 xk = *(const float4*)(g_xkj2 + (size_t)src*INT_EMB + l16*4);
        a.x *= xk.x; a.y *= xk.y; a.z *= xk.z; a.w *= xk.w;

        atomicAdd((float4*)(g_agg + (size_t)dst*INT_EMB + l16*4), a);
        __syncthreads();
    }
}

// ---------------- host launcher ----------------------------------------------
extern "C" void kernel_launch(void* const* d_in, const int* in_sizes, int n_in,
                              void* d_out, int out_size) {
    const float* m       = (const float*)d_in[0];
    const float* rbf     = (const float*)d_in[1];
    const float* sbf     = (const float*)d_in[2];
    const int*   src_idx = (const int*)d_in[3];
    const int*   dst_idx = (const int*)d_in[4];
    const float* W_rbf1  = (const float*)d_in[5];
    const float* W_rbf2  = (const float*)d_in[6];
    const float* W_sbf1  = (const float*)d_in[7];
    const float* W_sbf2  = (const float*)d_in[8];
    const float* W_ji    = (const float*)d_in[9];
    const float* b_ji    = (const float*)d_in[10];
    const float* W_kj    = (const float*)d_in[11];
    const float* b_kj    = (const float*)d_in[12];
    const float* W_down  = (const float*)d_in[13];
    const float* W_up    = (const float*)d_in[14];
    const float* Wb1     = (const float*)d_in[15];
    const float* bb1     = (const float*)d_in[16];
    const float* Wb2     = (const float*)d_in[17];
    const float* bb2     = (const float*)d_in[18];
    const float* W_final = (const float*)d_in[19];
    const float* b_final = (const float*)d_in[20];
    const float* Wa1     = (const float*)d_in[21];
    const float* ba1     = (const float*)d_in[22];
    const float* Wa2     = (const float*)d_in[23];
    const float* ba2     = (const float*)d_in[24];
    float* out = (float*)d_out;

    float *p_xji, *p_tmp, *p_upd, *p_xkj2, *p_agg;
    uint32_t* p_Bf;
    cudaGetSymbolAddress((void**)&p_xji,  g_xji);
    cudaGetSymbolAddress((void**)&p_tmp,  g_tmp);
    cudaGetSymbolAddress((void**)&p_upd,  g_upd);
    cudaGetSymbolAddress((void**)&p_xkj2, g_xkj2);
    cudaGetSymbolAddress((void**)&p_agg,  g_agg);
    cudaGetSymbolAddress((void**)&p_Bf,   g_Bf);

    const int GB = E_EDGES / 128;     // 2048
    // dyn smem: As + 2 B chunk buffers
    const int SM_N128K128 = (128*128 + 2*CHUNK_S*16*64)*4;   // 98304
    const int SM_N64K128  = (128*128 + 2*CHUNK_S*8*64)*4;    // 81920
    const int SM_N128K64  = (128*64  + 2*CHUNK_S*16*64)*4;   // 65536

    cudaFuncSetAttribute((const void*)gemm2_mma3, cudaFuncAttributeMaxDynamicSharedMemorySize, SM_N128K128);
    cudaFuncSetAttribute((const void*)gemm_mma3<128,128,false,true >, cudaFuncAttributeMaxDynamicSharedMemorySize, SM_N128K128);
    cudaFuncSetAttribute((const void*)gemm_mma3<64 ,128,false,false>, cudaFuncAttributeMaxDynamicSharedMemorySize, SM_N64K128);
    cudaFuncSetAttribute((const void*)gemm_mma3<128,64 ,false,true >, cudaFuncAttributeMaxDynamicSharedMemorySize, SM_N128K64);
    cudaFuncSetAttribute((const void*)resid_mma3, cudaFuncAttributeMaxDynamicSharedMemorySize, SM_N128K128);

    // ---- launch order: my #4 = gemm2_mma3 (overall #6 for ncu -s 5 -c 1) ----
    stage_Bg<<<128, 128>>>(W_ji, p_Bf + OFF_JI, 128, 128);            // 1
    stage_Bg<<<128, 128>>>(W_kj, p_Bf + OFF_KJ, 128, 128);            // 2
    fuse_wr_kernel<<<3, 256>>>(W_rbf1, W_rbf2);                       // 3

    // x_ji & tmp in one pass (shared A staging)                      // 4 <- profiled
    gemm2_mma3<<<GB,256,SM_N128K128>>>(m, p_Bf + OFF_JI, p_Bf + OFF_KJ,
                                       b_ji, b_kj, rbf, p_xji, p_tmp);

    zero_agg_kernel<<<(E_EDGES*INT_EMB/4)/256, 256>>>();              // 5
    stage_Bg<<<64 , 128>>>(W_down, p_Bf + OFF_DOWN, 128, 64);         // 6
    stage_Bg<<<64 , 128>>>(W_up,    p_Bf + OFF_UP,   64 , 128);
    stage_Bg<<<128, 128>>>(Wb1,     p_Bf + OFF_B1,   128, 128);
    stage_Bg<<<128, 128>>>(Wb2,     p_Bf + OFF_B2,   128, 128);
    stage_Bg<<<128, 128>>>(W_final, p_Bf + OFF_FIN,  128, 128);
    stage_Bg<<<128, 128>>>(Wa1,           p_Bf + OFF_A10, 128, 128);
    stage_Bg<<<128, 128>>>(Wa2,           p_Bf + OFF_A20, 128, 128);
    stage_Bg<<<128, 128>>>(Wa1 + 128*128, p_Bf + OFF_A11, 128, 128);
    stage_Bg<<<128, 128>>>(Wa2 + 128*128, p_Bf + OFF_A21, 128, 128);

    // x_kj2 = silu(tmp @ W_down)
    gemm_mma3<64 ,128,false,false><<<GB,256,SM_N64K128>>>(p_tmp, p_Bf + OFF_DOWN, nullptr, nullptr, nullptr, p_xkj2);

    // triplet message + segment sum
    triplet_kernel<<<4096, 256>>>(sbf, src_idx, dst_idx, W_sbf1, W_sbf2);

    // upd = x_ji + silu(agg @ W_up)
    gemm_mma3<128,64 ,false,true ><<<GB,256,SM_N128K64>>>(p_agg, p_Bf + OFF_UP, nullptr, p_xji, nullptr, p_upd);
    // residual-before (N_BEFORE=1), in-place
    resid_mma3<<<GB,256,SM_N128K128>>>(p_upd, p_Bf + OFF_B1, bb1, p_Bf + OFF_B2, bb2, p_upd);
    // final: out = m + silu(upd @ W_final + b_final)
    gemm_mma3<128,128,false,true ><<<GB,256,SM_N128K128>>>(p_upd, p_Bf + OFF_FIN, b_final, m, nullptr, out);
    // residual-after (N_AFTER=2), in-place on out
    resid_mma3<<<GB,256,SM_N128K128>>>(out, p_Bf + OFF_A10, ba1,       p_Bf + OFF_A20, ba2,       out);
    resid_mma3<<<GB,256,SM_N128K128>>>(out, p_Bf + OFF_A11, ba1 + 128, p_Bf + OFF_A21, ba2 + 128, out);
}

// round 15
// speedup vs baseline: 1.4454x; 1.1188x over previous
#include <cuda_runtime.h>
#include <cuda_fp16.h>
#include <cstdint>

typedef unsigned long long ull;

#define EMB 128
#define INT_EMB 64
#define NRAD 6
#define NSR 42
#define BASIS 8
#define E_EDGES 262144
#define T_TRIP 2097152

// ---------------- scratch (device globals) ------------------------------------
__device__ float g_Wr[NRAD*EMB];
__device__ float g_xji[(size_t)E_EDGES*EMB];
__device__ float g_tmp[(size_t)E_EDGES*EMB];
__device__ float g_upd[(size_t)E_EDGES*EMB];
__device__ float g_xkj2[(size_t)E_EDGES*INT_EMB];
__device__ float g_agg[(size_t)E_EDGES*INT_EMB];
__device__ uint32_t g_Bh[81920];   // all weights, fp16 fragment layout (m16n8k16)

// B-frag offsets (u32 elements; matrix = K*N/2 u32)
#define OFF_JI   0
#define OFF_KJ   8192
#define OFF_DOWN 16384
#define OFF_UP   20480
#define OFF_B1   24576
#define OFF_B2   32768
#define OFF_FIN  40960
#define OFF_A10  49152
#define OFF_A20  57344
#define OFF_A11  65536
#define OFF_A21  73728

// ---------------- helpers ------------------------------------------------------
__device__ __forceinline__ float silu_f(float x){ return x * (1.0f/(1.0f + __expf(-x))); }
__device__ __forceinline__ uint32_t pack_h2(float lo, float hi){
    __half2 h = __floats2half2_rn(lo, hi);
    return *(uint32_t*)&h;
}
__device__ __forceinline__ void mma_f16(float* c, const uint32_t* a, const uint32_t* b){
    asm volatile("mma.sync.aligned.m16n8k16.row.col.f32.f16.f16.f32 "
        "{%0,%1,%2,%3}, {%4,%5,%6,%7}, {%8,%9}, {%0,%1,%2,%3};"
        : "+f"(c[0]), "+f"(c[1]), "+f"(c[2]), "+f"(c[3])
        : "r"(a[0]), "r"(a[1]), "r"(a[2]), "r"(a[3]), "r"(b[0]), "r"(b[1]));
}

// ---------------- K0: fuse W_rbf1 @ W_rbf2 -> g_Wr ----------------------------
__global__ void fuse_wr_kernel(const float* __restrict__ W1, const float* __restrict__ W2) {
    int i = blockIdx.x * blockDim.x + threadIdx.x;
    if (i < NRAD * EMB) {
        int r = i / EMB, n = i % EMB;
        float s = 0.f;
#pragma unroll
        for (int b = 0; b < BASIS; b++) s += W1[r*BASIS + b] * W2[b*EMB + n];
        g_Wr[i] = s;
    }
}

// ---------------- zero g_agg --------------------------------------------------
__global__ void zero_agg_kernel() {
    size_t i = (size_t)blockIdx.x * blockDim.x + threadIdx.x;
    float4 z = {0.f, 0.f, 0.f, 0.f};
    ((float4*)g_agg)[i] = z;
}

// ---------------- B fragment precompute (fp16 m16n8k16 layout) ------------------
// element (k,n): s=k/16, kk=k%16, rg=kk/8, lp=(kk%8)/2, lane=(n%8)*4+lp, nt=n/8
// u32 packs fp16 {k even, k odd}
__global__ void stage_Bh(const float* __restrict__ W, uint32_t* __restrict__ out,
                         int K, int N) {
    int i = blockIdx.x * 128 + threadIdx.x;
    if (i >= (K/2)*N) return;
    int kp = i / N, n = i % N;
    int k = kp * 2;
    uint32_t h = pack_h2(W[(size_t)k*N + n], W[(size_t)(k+1)*N + n]);
    int NT = N/8;
    int s = k >> 4, kk = k & 15;
    int rg = kk >> 3, lp = (kk & 7) >> 1;
    int lane = ((n & 7) << 2) | lp;
    int nt = n >> 3;
    out[((s*NT + nt)*32 + lane)*2 + rg] = h;
}

// ---------------- A staging: fp16 pairs, row-major, XOR-swizzled ----------------
// As: u32[128][K/2], u32 col c swizzled by ((row&7)<<2)
template<int K>
__device__ __forceinline__ void stage_Ah(const float* __restrict__ A, size_t m0,
                                         uint32_t* __restrict__ As, int tid) {
    constexpr int QPR = K/4, RW = K/2;
    for (int i = tid; i < 128*QPR; i += 256) {
        int row = i / QPR, q4 = i % QPR;
        const float4 a4 = *(const float4*)&A[(m0+row)*K + q4*4];
        uint2 t;
        t.x = pack_h2(a4.x, a4.y);
        t.y = pack_h2(a4.z, a4.w);
        int c = (q4*2) ^ ((row & 7) << 2);
        *(uint2*)&As[row*RW + c] = t;
    }
}

// ---------------- cp.async chunk copy ------------------------------------------
template<int CHUNK_U32>
__device__ __forceinline__ void cp_chunk(uint32_t* __restrict__ Bs,
                                         const uint32_t* __restrict__ Bf, int tid) {
    constexpr int NCP = (CHUNK_U32*4) / (256*16);
    const uint32_t sdst = (uint32_t)__cvta_generic_to_shared(Bs);
#pragma unroll
    for (int i = 0; i < NCP; i++) {
        const int off = (tid + i*256) * 16;
        asm volatile("cp.async.cg.shared.global [%0], [%1], 16;"
            :: "r"(sdst + (uint32_t)off), "l"((const char*)Bf + off) : "memory");
    }
}

// ---------------- fp16 mainloop: A LDS + B via cp.async chunks ------------------
// K = fp16 depth; KS = K/16 steps; acc0 rows [0,16), acc1 rows [16,32) of warp slab
template<int K, int NT, int WNT>
__device__ __forceinline__ void mainloop_h(const uint32_t* __restrict__ As,
                                           uint32_t* __restrict__ Bs,
                                           const uint32_t* __restrict__ Bf,
                                           int mp, int nt0, int lane, int tid,
                                           float (*acc0)[4], float (*acc1)[4]) {
    constexpr int KS = K/16;
    constexpr int CH = (KS < 4) ? KS : 4;
    constexpr int C  = KS/CH;
    constexpr int CHUNK_U32 = CH*NT*64;
    constexpr int RW = K/2;
    const int q = lane >> 2, sw = q << 2;
    const int rowA0 = (mp*32 + q) * RW;
    const int rowA1 = rowA0 + 16*RW;

    cp_chunk<CHUNK_U32>(Bs, Bf, tid);
    asm volatile("cp.async.commit_group;" ::: "memory");

#pragma unroll
    for (int c = 0; c < C; c++) {
        if (c + 1 < C) {
            cp_chunk<CHUNK_U32>(Bs + ((c+1)&1)*CHUNK_U32, Bf + (c+1)*CHUNK_U32, tid);
            asm volatile("cp.async.commit_group;" ::: "memory");
            asm volatile("cp.async.wait_group 1;" ::: "memory");
        } else {
            asm volatile("cp.async.wait_group 0;" ::: "memory");
        }
        __syncthreads();
        const uint32_t* Bc = Bs + (c&1)*CHUNK_U32;
#pragma unroll
        for (int sl = 0; sl < CH; sl++) {
            const int s = c*CH + sl;
            const int cb = s*8 + (lane & 3);
            uint32_t a[2][4];
            a[0][0] = As[rowA0        + (cb ^ sw)];
            a[0][1] = As[rowA0 + 8*RW + (cb ^ sw)];
            a[0][2] = As[rowA0        + ((cb+4) ^ sw)];
            a[0][3] = As[rowA0 + 8*RW + ((cb+4) ^ sw)];
            a[1][0] = As[rowA1        + (cb ^ sw)];
            a[1][1] = As[rowA1 + 8*RW + (cb ^ sw)];
            a[1][2] = As[rowA1        + ((cb+4) ^ sw)];
            a[1][3] = As[rowA1 + 8*RW + ((cb+4) ^ sw)];
#pragma unroll
            for (int j = 0; j < WNT; j++) {
                uint2 b = *(const uint2*)&Bc[((sl*NT + nt0 + j)*32 + lane)*2];
                mma_f16(acc0[j], a[0], (const uint32_t*)&b);
                mma_f16(acc1[j], a[1], (const uint32_t*)&b);
            }
        }
        __syncthreads();
    }
}
template<int W4>
__device__ __forceinline__ void zero_acc(float (*acc)[4]) {
#pragma unroll
    for (int i = 0; i < W4; i++)
#pragma unroll
        for (int e = 0; e < 4; e++) acc[i][e] = 0.f;
}

// ---------------- generic fused GEMM -------------------------------------------
template<int N, int K, bool MUL_RBF, bool ADD_RES>
__global__ __launch_bounds__(256, 2)
void gemm_h(const float* __restrict__ A, const uint32_t* __restrict__ Bf,
            const float* __restrict__ bias, const float* __restrict__ res,
            const float* __restrict__ rbf, float* __restrict__ out) {
    constexpr int NT = N/8, WNT = NT/2;
    extern __shared__ __align__(16) uint32_t dyn[];
    uint32_t* As = dyn;
    uint32_t* Bs = dyn + 128*(K/2);
    __shared__ float s_Wr[MUL_RBF ? NRAD*EMB : 1];

    const int tid = threadIdx.x, lane = tid & 31, w = tid >> 5;
    const size_t m0 = (size_t)blockIdx.x * 128;
    const int mp = w >> 1;
    const int nt0 = (w & 1) * WNT;
    const int q = lane >> 2;

    if (MUL_RBF) for (int i = tid; i < NRAD*EMB; i += 256) s_Wr[i] = g_Wr[i];
    stage_Ah<K>(A, m0, As, tid);
    __syncthreads();

    float acc[2][WNT][4];
    zero_acc<2*WNT>(&acc[0][0]);
    mainloop_h<K, NT, WNT>(As, Bs, Bf, mp, nt0, lane, tid, acc[0], acc[1]);

#pragma unroll
    for (int i = 0; i < 2; i++) {
        const size_t r_lo = m0 + mp*32 + i*16 + q;
        const size_t r_hi = r_lo + 8;
        float r6lo[NRAD], r6hi[NRAD];
        if (MUL_RBF) {
#pragma unroll
            for (int l = 0; l < NRAD; l++) { r6lo[l] = rbf[r_lo*NRAD + l]; r6hi[l] = rbf[r_hi*NRAD + l]; }
        }
#pragma unroll
        for (int j = 0; j < WNT; j++) {
            const int col = (nt0 + j)*8 + (lane & 3)*2;
            float2 bj = make_float2(0.f, 0.f);
            if (bias) bj = *(const float2*)&bias[col];
            float v00 = silu_f(acc[i][j][0] + bj.x);
            float v01 = silu_f(acc[i][j][1] + bj.y);
            float v10 = silu_f(acc[i][j][2] + bj.x);
            float v11 = silu_f(acc[i][j][3] + bj.y);
            if (MUL_RBF) {
                float e00=0.f,e01=0.f,e10=0.f,e11=0.f;
#pragma unroll
                for (int l = 0; l < NRAD; l++) {
                    const float w0 = s_Wr[l*EMB + col], w1 = s_Wr[l*EMB + col + 1];
                    e00 += r6lo[l]*w0; e01 += r6lo[l]*w1;
                    e10 += r6hi[l]*w0; e11 += r6hi[l]*w1;
                }
                v00 *= e00; v01 *= e01; v10 *= e10; v11 *= e11;
            }
            if (ADD_RES) {
                const float2 rl = *(const float2*)&res[r_lo*N + col];
                const float2 rh = *(const float2*)&res[r_hi*N + col];
                v00 += rl.x; v01 += rl.y; v10 += rh.x; v11 += rh.y;
            }
            float2 o0; o0.x = v00; o0.y = v01;
            float2 o1; o1.x = v10; o1.y = v11;
            *(float2*)&out[r_lo*N + col] = o0;
            *(float2*)&out[r_hi*N + col] = o1;
        }
    }
}

// ---------------- fused ji+kj kernel -------------------------------------------
__global__ __launch_bounds__(256, 2)
void gemm2_h(const float* __restrict__ m,
             const uint32_t* __restrict__ Bf_ji, const uint32_t* __restrict__ Bf_kj,
             const float* __restrict__ b_ji, const float* __restrict__ b_kj,
             const float* __restrict__ rbf,
             float* __restrict__ out_ji, float* __restrict__ out_kj) {
    constexpr int NT = 16, WNT = 8;
    extern __shared__ __align__(16) uint32_t dyn[];
    uint32_t* As = dyn;
    uint32_t* Bs = dyn + 128*64;
    __shared__ float s_Wr[NRAD*EMB];

    const int tid = threadIdx.x, lane = tid & 31, w = tid >> 5;
    const size_t m0 = (size_t)blockIdx.x * 128;
    const int mp = w >> 1;
    const int nt0 = (w & 1) * WNT;
    const int q = lane >> 2;

    for (int i = tid; i < NRAD*EMB; i += 256) s_Wr[i] = g_Wr[i];
    stage_Ah<128>(m, m0, As, tid);
    __syncthreads();

    float acc[2][WNT][4];

    // ======== phase 1: x_ji ========
    zero_acc<2*WNT>(&acc[0][0]);
    mainloop_h<128, NT, WNT>(As, Bs, Bf_ji, mp, nt0, lane, tid, acc[0], acc[1]);
#pragma unroll
    for (int i = 0; i < 2; i++) {
        const size_t r_lo = m0 + mp*32 + i*16 + q;
        const size_t r_hi = r_lo + 8;
#pragma unroll
        for (int j = 0; j < WNT; j++) {
            const int col = (nt0 + j)*8 + (lane & 3)*2;
            const float2 bj = *(const float2*)&b_ji[col];
            float2 o0, o1;
            o0.x = silu_f(acc[i][j][0] + bj.x);
            o0.y = silu_f(acc[i][j][1] + bj.y);
            o1.x = silu_f(acc[i][j][2] + bj.x);
            o1.y = silu_f(acc[i][j][3] + bj.y);
            *(float2*)&out_ji[r_lo*128 + col] = o0;
            *(float2*)&out_ji[r_hi*128 + col] = o1;
        }
    }

    // ======== phase 2: tmp (kj * rbf_env) ========
    zero_acc<2*WNT>(&acc[0][0]);
    mainloop_h<128, NT, WNT>(As, Bs, Bf_kj, mp, nt0, lane, tid, acc[0], acc[1]);
#pragma unroll
    for (int i = 0; i < 2; i++) {
        const size_t r_lo = m0 + mp*32 + i*16 + q;
        const size_t r_hi = r_lo + 8;
        float r6lo[NRAD], r6hi[NRAD];
#pragma unroll
        for (int l = 0; l < NRAD; l++) { r6lo[l] = rbf[r_lo*NRAD + l]; r6hi[l] = rbf[r_hi*NRAD + l]; }
#pragma unroll
        for (int j = 0; j < WNT; j++) {
            const int col = (nt0 + j)*8 + (lane & 3)*2;
            const float2 bj = *(const float2*)&b_kj[col];
            float e00=0.f,e01=0.f,e10=0.f,e11=0.f;
#pragma unroll
            for (int l = 0; l < NRAD; l++) {
                const float w0 = s_Wr[l*EMB + col], w1 = s_Wr[l*EMB + col + 1];
                e00 += r6lo[l]*w0; e01 += r6lo[l]*w1;
                e10 += r6hi[l]*w0; e11 += r6hi[l]*w1;
            }
            float2 o0, o1;
            o0.x = silu_f(acc[i][j][0] + bj.x) * e00;
            o0.y = silu_f(acc[i][j][1] + bj.y) * e01;
            o1.x = silu_f(acc[i][j][2] + bj.x) * e10;
            o1.y = silu_f(acc[i][j][3] + bj.y) * e11;
            *(float2*)&out_kj[r_lo*128 + col] = o0;
            *(float2*)&out_kj[r_hi*128 + col] = o1;
        }
    }
}

// ---------------- fused residual block -----------------------------------------
__global__ __launch_bounds__(256, 2)
void resid_h(const float* __restrict__ X,
             const uint32_t* __restrict__ B1f, const float* __restrict__ b1,
             const uint32_t* __restrict__ B2f, const float* __restrict__ b2,
             float* __restrict__ out) {
    constexpr int NT = 16, WNT = 8, RW = 64;
    extern __shared__ __align__(16) uint32_t dyn[];
    uint32_t* As = dyn;
    uint32_t* Bs = dyn + 128*RW;

    const int tid = threadIdx.x, lane = tid & 31, w = tid >> 5;
    const size_t m0 = (size_t)blockIdx.x * 128;
    const int mp = w >> 1;
    const int nt0 = (w & 1) * WNT;
    const int q = lane >> 2;
    const int sw = q << 2;

    stage_Ah<128>(X, m0, As, tid);
    __syncthreads();

    float acc[2][WNT][4];
    zero_acc<2*WNT>(&acc[0][0]);
    mainloop_h<128, NT, WNT>(As, Bs, B1f, mp, nt0, lane, tid, acc[0], acc[1]);
    // mainloop ends with __syncthreads(): all A reads done

    // epilogue1: h = silu(acc + b1) -> back into As (fp16 packed)
#pragma unroll
    for (int i = 0; i < 2; i++) {
        const int rl = mp*32 + i*16 + q;
#pragma unroll
        for (int j = 0; j < WNT; j++) {
            const int cj = (nt0 + j)*8 + (lane & 3)*2;
            const int cjp = cj >> 1;   // u32 col
            const float2 bj = *(const float2*)&b1[cj];
            As[rl*RW     + (cjp ^ sw)] = pack_h2(silu_f(acc[i][j][0] + bj.x),
                                                 silu_f(acc[i][j][1] + bj.y));
            As[(rl+8)*RW + (cjp ^ sw)] = pack_h2(silu_f(acc[i][j][2] + bj.x),
                                                 silu_f(acc[i][j][3] + bj.y));
        }
    }
    __syncthreads();

    zero_acc<2*WNT>(&acc[0][0]);
    mainloop_h<128, NT, WNT>(As, Bs, B2f, mp, nt0, lane, tid, acc[0], acc[1]);

    // epilogue2: out = X + silu(acc + b2)
#pragma unroll
    for (int i = 0; i < 2; i++) {
        const size_t r_lo = m0 + mp*32 + i*16 + q;
        const size_t r_hi = r_lo + 8;
#pragma unroll
        for (int j = 0; j < WNT; j++) {
            const int col = (nt0 + j)*8 + (lane & 3)*2;
            const float2 bj = *(const float2*)&b2[col];
            const float2 xl = *(const float2*)&X[r_lo*128 + col];
            const float2 xh = *(const float2*)&X[r_hi*128 + col];
            float2 o0, o1;
            o0.x = xl.x + silu_f(acc[i][j][0] + bj.x);
            o0.y = xl.y + silu_f(acc[i][j][1] + bj.y);
            o1.x = xh.x + silu_f(acc[i][j][2] + bj.x);
            o1.y = xh.y + silu_f(acc[i][j][3] + bj.y);
            *(float2*)&out[r_lo*128 + col] = o0;
            *(float2*)&out[r_hi*128 + col] = o1;
        }
    }
}

// ---------------- triplet kernel (unchanged, passes) ---------------------------
__global__ __launch_bounds__(256)
void triplet_kernel(const float* __restrict__ sbf,
                    const int* __restrict__ src_idx,
                    const int* __restrict__ dst_idx,
                    const float* __restrict__ W1,
                    const float* __restrict__ W2) {
    __shared__ float sbf_s[16*NSR];
    __shared__ float W1s[NSR*BASIS];
    __shared__ __align__(16) float W2s[BASIS*INT_EMB];
    __shared__ float t8[16][BASIS];

    const int tid = threadIdx.x;
    for (int i = tid; i < NSR*BASIS; i += 256) W1s[i] = W1[i];
    for (int i = tid; i < BASIS*INT_EMB; i += 256) W2s[i] = W2[i];

    const int ngroups = T_TRIP / 16;
    const int half = tid >> 4;
    const int l16  = tid & 15;

    for (int g = blockIdx.x; g < ngroups; g += gridDim.x) {
        const size_t base = (size_t)g * (16*NSR);
        for (int i = tid; i < 16*NSR; i += 256) sbf_s[i] = sbf[base + i];
        __syncthreads();

        if (tid < 128) {
            int tt = tid >> 3, j = tid & 7;
            float s = 0.f;
#pragma unroll
            for (int r = 0; r < NSR; r++) s += sbf_s[tt*NSR + r] * W1s[r*BASIS + j];
            t8[tt][j] = s;
        }
        __syncthreads();

        const int t = g*16 + half;
        const int src = src_idx[t];
        const int dst = dst_idx[t];

        float4 a = {0.f, 0.f, 0.f, 0.f};
#pragma unroll
        for (int j = 0; j < BASIS; j++) {
            const float tv = t8[half][j];
            const float4 w = *(const float4*)&W2s[j*INT_EMB + l16*4];
            a.x += tv*w.x; a.y += tv*w.y; a.z += tv*w.z; a.w += tv*w.w;
        }
        const float4 xk = *(const float4*)(g_xkj2 + (size_t)src*INT_EMB + l16*4);
        a.x *= xk.x; a.y *= xk.y; a.z *= xk.z; a.w *= xk.w;

        atomicAdd((float4*)(g_agg + (size_t)dst*INT_EMB + l16*4), a);
        __syncthreads();
    }
}

// ---------------- host launcher ----------------------------------------------
extern "C" void kernel_launch(void* const* d_in, const int* in_sizes, int n_in,
                              void* d_out, int out_size) {
    const float* m       = (const float*)d_in[0];
    const float* rbf     = (const float*)d_in[1];
    const float* sbf     = (const float*)d_in[2];
    const int*   src_idx = (const int*)d_in[3];
    const int*   dst_idx = (const int*)d_in[4];
    const float* W_rbf1  = (const float*)d_in[5];
    const float* W_rbf2  = (const float*)d_in[6];
    const float* W_sbf1  = (const float*)d_in[7];
    const float* W_sbf2  = (const float*)d_in[8];
    const float* W_ji    = (const float*)d_in[9];
    const float* b_ji    = (const float*)d_in[10];
    const float* W_kj    = (const float*)d_in[11];
    const float* b_kj    = (const float*)d_in[12];
    const float* W_down  = (const float*)d_in[13];
    const float* W_up    = (const float*)d_in[14];
    const float* Wb1     = (const float*)d_in[15];
    const float* bb1     = (const float*)d_in[16];
    const float* Wb2     = (const float*)d_in[17];
    const float* bb2     = (const float*)d_in[18];
    const float* W_final = (const float*)d_in[19];
    const float* b_final = (const float*)d_in[20];
    const float* Wa1     = (const float*)d_in[21];
    const float* ba1     = (const float*)d_in[22];
    const float* Wa2     = (const float*)d_in[23];
    const float* ba2     = (const float*)d_in[24];
    float* out = (float*)d_out;

    float *p_xji, *p_tmp, *p_upd, *p_xkj2, *p_agg;
    uint32_t* p_Bh;
    cudaGetSymbolAddress((void**)&p_xji,  g_xji);
    cudaGetSymbolAddress((void**)&p_tmp,  g_tmp);
    cudaGetSymbolAddress((void**)&p_upd,  g_upd);
    cudaGetSymbolAddress((void**)&p_xkj2, g_xkj2);
    cudaGetSymbolAddress((void**)&p_agg,  g_agg);
    cudaGetSymbolAddress((void**)&p_Bh,   g_Bh);

    const int GB = E_EDGES / 128;     // 2048
    // dyn smem (u32 words * 4): As(128*K/2) + B chunk buffers
    const int SM_N128K128 = (128*64 + 2*4*16*64)*4;   // 32768 + 32768 = 65536
    const int SM_N64K128  = (128*64 + 2*4*8*64)*4;    // 32768 + 16384 = 49152
    const int SM_N128K64  = (128*32 + 1*4*16*64)*4;   // 16384 + 16384 = 32768

    cudaFuncSetAttribute((const void*)gemm2_h, cudaFuncAttributeMaxDynamicSharedMemorySize, SM_N128K128);
    cudaFuncSetAttribute((const void*)gemm_h<128,128,false,true >, cudaFuncAttributeMaxDynamicSharedMemorySize, SM_N128K128);
    cudaFuncSetAttribute((const void*)gemm_h<64 ,128,false,false>, cudaFuncAttributeMaxDynamicSharedMemorySize, SM_N64K128);
    cudaFuncSetAttribute((const void*)gemm_h<128,64 ,false,true >, cudaFuncAttributeMaxDynamicSharedMemorySize, SM_N128K64);
    cudaFuncSetAttribute((const void*)resid_h, cudaFuncAttributeMaxDynamicSharedMemorySize, SM_N128K128);

    // ---- launch order: my #4 = gemm2_h (overall #6 for ncu -s 5 -c 1) ----
    stage_Bh<<<64, 128>>>(W_ji, p_Bh + OFF_JI, 128, 128);             // 1
    stage_Bh<<<64, 128>>>(W_kj, p_Bh + OFF_KJ, 128, 128);             // 2
    fuse_wr_kernel<<<3, 256>>>(W_rbf1, W_rbf2);                       // 3

    // x_ji & tmp in one pass (shared A staging)                      // 4 <- profiled
    gemm2_h<<<GB,256,SM_N128K128>>>(m, p_Bh + OFF_JI, p_Bh + OFF_KJ,
                                    b_ji, b_kj, rbf, p_xji, p_tmp);

    zero_agg_kernel<<<(E_EDGES*INT_EMB/4)/256, 256>>>();              // 5
    stage_Bh<<<32, 128>>>(W_down, p_Bh + OFF_DOWN, 128, 64);          // 6
    stage_Bh<<<32, 128>>>(W_up,    p_Bh + OFF_UP,   64 , 128);
    stage_Bh<<<64, 128>>>(Wb1,     p_Bh + OFF_B1,   128, 128);
    stage_Bh<<<64, 128>>>(Wb2,     p_Bh + OFF_B2,   128, 128);
    stage_Bh<<<64, 128>>>(W_final, p_Bh + OFF_FIN,  128, 128);
    stage_Bh<<<64, 128>>>(Wa1,           p_Bh + OFF_A10, 128, 128);
    stage_Bh<<<64, 128>>>(Wa2,           p_Bh + OFF_A20, 128, 128);
    stage_Bh<<<64, 128>>>(Wa1 + 128*128, p_Bh + OFF_A11, 128, 128);
    stage_Bh<<<64, 128>>>(Wa2 + 128*128, p_Bh + OFF_A21, 128, 128);

    // x_kj2 = silu(tmp @ W_down)
    gemm_h<64 ,128,false,false><<<GB,256,SM_N64K128>>>(p_tmp, p_Bh + OFF_DOWN, nullptr, nullptr, nullptr, p_xkj2);

    // triplet message + segment sum
    triplet_kernel<<<4096, 256>>>(sbf, src_idx, dst_idx, W_sbf1, W_sbf2);

    // upd = x_ji + silu(agg @ W_up)
    gemm_h<128,64 ,false,true ><<<GB,256,SM_N128K64>>>(p_agg, p_Bh + OFF_UP, nullptr, p_xji, nullptr, p_upd);
    // residual-before (N_BEFORE=1), in-place
    resid_h<<<GB,256,SM_N128K128>>>(p_upd, p_Bh + OFF_B1, bb1, p_Bh + OFF_B2, bb2, p_upd);
    // final: out = m + silu(upd @ W_final + b_final)
    gemm_h<128,128,false,true ><<<GB,256,SM_N128K128>>>(p_upd, p_Bh + OFF_FIN, b_final, m, nullptr, out);
    // residual-after (N_AFTER=2), in-place on out
    resid_h<<<GB,256,SM_N128K128>>>(out, p_Bh + OFF_A10, ba1,       p_Bh + OFF_A20, ba2,       out);
    resid_h<<<GB,256,SM_N128K128>>>(out, p_Bh + OFF_A11, ba1 + 128, p_Bh + OFF_A21, ba2 + 128, out);
}